// round 5
// baseline (speedup 1.0000x reference)
#include <cuda_runtime.h>
#include <cuda_fp16.h>
#include <math.h>
#include <stdint.h>

#define Bb 32
#define Ss 2048
#define Hh 1024
#define Uu 1024
#define Mm (Bb*Ss)

// ---------------- device scratch (static, no runtime alloc) ----------------
__device__ float g_query[Bb*Uu];                     // q[b,u] = hidden_t@W2 + b2
__device__ float g_score[Bb*Ss];                     // scores -> softmax weights
__device__ __align__(16) __half g_w1t_hi[Uu*Hh];     // W1^T hi  [u][k]
__device__ __align__(16) __half g_w1t_lo[Uu*Hh];     // W1^T lo  [u][k]
__device__ __align__(16) __half g_a_hi[(size_t)Mm*Hh];  // hiddens hi [row][k]
__device__ __align__(16) __half g_a_lo[(size_t)Mm*Hh];  // hiddens lo [row][k]

// ---------------- PTX helpers (non-'a' features only: valid on sm_103) -----
__device__ __forceinline__ void cp_async16(uint32_t dst, const void* src) {
    asm volatile("cp.async.cg.shared.global [%0], [%1], 16;\n"
                 :: "r"(dst), "l"(src) : "memory");
}
#define CP_COMMIT() asm volatile("cp.async.commit_group;\n" ::: "memory")
#define CP_WAIT0()  asm volatile("cp.async.wait_group 0;\n" ::: "memory")

__device__ __forceinline__ void ldsm4(uint32_t r[4], uint32_t addr) {
    asm volatile("ldmatrix.sync.aligned.m8n8.x4.shared.b16 {%0,%1,%2,%3}, [%4];"
                 : "=r"(r[0]), "=r"(r[1]), "=r"(r[2]), "=r"(r[3]) : "r"(addr));
}
__device__ __forceinline__ void mma16816(float c[4], const uint32_t a[4],
                                         uint32_t b0, uint32_t b1) {
    asm volatile("mma.sync.aligned.m16n8k16.row.col.f32.f16.f16.f32 "
                 "{%0,%1,%2,%3}, {%4,%5,%6,%7}, {%8,%9}, {%0,%1,%2,%3};"
                 : "+f"(c[0]), "+f"(c[1]), "+f"(c[2]), "+f"(c[3])
                 : "r"(a[0]), "r"(a[1]), "r"(a[2]), "r"(a[3]), "r"(b0), "r"(b1));
}

__device__ __forceinline__ float ftanh(float x) {
    const float cx = fminf(fmaxf(x, -9.f), 9.f);
    const float e  = __expf(2.f * cx);
    return __fdividef(e - 1.f, e + 1.f);
}

// ---------------- SMEM layout ----------------
#define OFF_BQ   0
#define OFF_VS   4096
#define OFF_SROW 8192
#define OFF_TILE 8704
#define A_HI 0
#define A_LO 16384
#define B_HI 32768
#define B_LO 49152
#define BUF_SZ 65536
#define SMEM_TOTAL (OFF_TILE + 2*BUF_SZ)   // 139776 bytes

#define NPASS  8     // u-tiles of 128
#define NCHUNK 16    // K chunks of 64
#define NTHR   512   // 16 warps: 4(M) x 4(N)

// ---------------------------------------------------------------------------
// prep: hiddens fp32 -> fp16 hi/lo (coalesced, one float4 per thread)
// ---------------------------------------------------------------------------
__global__ void a_split_kernel(const float* __restrict__ hiddens)
{
    const size_t i = (size_t)blockIdx.x * 256 + threadIdx.x;  // float4 index
    const float4 v = ((const float4*)hiddens)[i];

    const __half hx = __float2half_rn(v.x), hy = __float2half_rn(v.y);
    const __half hz = __float2half_rn(v.z), hw = __float2half_rn(v.w);
    const __half lx = __float2half_rn(v.x - __half2float(hx));
    const __half ly = __float2half_rn(v.y - __half2float(hy));
    const __half lz = __float2half_rn(v.z - __half2float(hz));
    const __half lw = __float2half_rn(v.w - __half2float(hw));

    __half2 h01 = __halves2half2(hx, hy), h23 = __halves2half2(hz, hw);
    __half2 l01 = __halves2half2(lx, ly), l23 = __halves2half2(lz, lw);
    uint2 hv, lv;
    hv.x = *reinterpret_cast<uint32_t*>(&h01);
    hv.y = *reinterpret_cast<uint32_t*>(&h23);
    lv.x = *reinterpret_cast<uint32_t*>(&l01);
    lv.y = *reinterpret_cast<uint32_t*>(&l23);
    ((uint2*)g_a_hi)[i] = hv;
    ((uint2*)g_a_lo)[i] = lv;
}

// ---------------------------------------------------------------------------
// prep: W1^T hi/lo (fp16 split) from W1 [H,U]
// ---------------------------------------------------------------------------
__global__ void w1t_kernel(const float* __restrict__ W1)
{
    __shared__ float t[32][33];
    const int k0 = blockIdx.x * 32, u0 = blockIdx.y * 32;
    const int x = threadIdx.x, y = threadIdx.y;   // 32 x 8
#pragma unroll
    for (int i = 0; i < 32; i += 8)
        t[y + i][x] = W1[(size_t)(k0 + y + i) * Uu + u0 + x];
    __syncthreads();
#pragma unroll
    for (int i = 0; i < 32; i += 8) {
        const float v = t[x][y + i];
        const __half hi = __float2half_rn(v);
        const float res = v - __half2float(hi);
        const size_t o = (size_t)(u0 + y + i) * Hh + k0 + x;
        g_w1t_hi[o] = hi;
        g_w1t_lo[o] = __float2half_rn(res);
    }
}

// ---------------------------------------------------------------------------
// query[b,u] = hidden_t@W2 + b2
// ---------------------------------------------------------------------------
__global__ void query_kernel(const float* __restrict__ hidden_t,
                             const float* __restrict__ W2,
                             const float* __restrict__ b2)
{
    __shared__ float ht[Hh];
    int b = blockIdx.x;
    int u = blockIdx.y * 128 + threadIdx.x;
    for (int i = threadIdx.x; i < Hh; i += 128) ht[i] = hidden_t[b * Hh + i];
    __syncthreads();
    float acc = b2[u];
#pragma unroll 8
    for (int h = 0; h < Hh; ++h)
        acc += ht[h] * W2[h * Uu + u];
    g_query[b * Uu + u] = acc;
}

// ---------------------------------------------------------------------------
// chunk loader: A hi/lo (128x64) + B hi/lo (128x64) all via cp.async
// rows of 64 fp16 = 128B, xor-swizzled per 8-row group
// ---------------------------------------------------------------------------
__device__ __forceinline__ void load_chunk(int row0, int u0, int k0,
                                           uint32_t sb, uint32_t bufoff, int tid)
{
    const uint32_t base = sb + OFF_TILE + bufoff;
    // A: 128 rows x 8 segs: 1024 segs / 512 thr = 2 each (hi + lo)
#pragma unroll
    for (int i = 0; i < 2; ++i) {
        const int lin = i * NTHR + tid;
        const int n = lin >> 3, sg = lin & 7;
        const uint32_t off = (uint32_t)(n * 128 + ((sg * 16) ^ ((n & 7) * 16)));
        const size_t src = (size_t)(row0 + n) * Hh + k0 + sg * 8;
        cp_async16(base + A_HI + off, g_a_hi + src);
        cp_async16(base + A_LO + off, g_a_lo + src);
    }
    // B: 128 rows x 8 segs: 1024 segs / 512 thr = 2 each (hi + lo)
#pragma unroll
    for (int i = 0; i < 2; ++i) {
        const int lin = i * NTHR + tid;
        const int n = lin >> 3, sg = lin & 7;
        const uint32_t off = (uint32_t)(n * 128 + ((sg * 16) ^ ((n & 7) * 16)));
        const size_t src = (size_t)(u0 + n) * Hh + k0 + sg * 8;
        cp_async16(base + B_HI + off, g_w1t_hi + src);
        cp_async16(base + B_LO + off, g_w1t_lo + src);
    }
}

// ---------------------------------------------------------------------------
// compute one K=64 chunk: acc += Ah*Bh + Al*Bh + Ah*Bl
// per warp: 32 rows (2 mt) x 32 cols (2 nt ldsm -> 4 n8)
// ---------------------------------------------------------------------------
__device__ __forceinline__ void compute_chunk(float acc[2][4][4],
                                              const uint32_t a_base[2],
                                              const uint32_t b_base[2],
                                              int msk, int lk16, uint32_t bufoff)
{
#pragma unroll
    for (int ks = 0; ks < 4; ++ks) {
        const uint32_t koff = (uint32_t)((ks * 32 + lk16) ^ msk);
        uint32_t ah[2][4], bh[2][4];
#pragma unroll
        for (int mt = 0; mt < 2; ++mt) ldsm4(ah[mt], a_base[mt] + bufoff + koff);
#pragma unroll
        for (int nt = 0; nt < 2; ++nt) ldsm4(bh[nt], b_base[nt] + bufoff + koff);
#pragma unroll
        for (int mt = 0; mt < 2; ++mt)
#pragma unroll
            for (int nt = 0; nt < 2; ++nt) {
                mma16816(acc[mt][nt*2+0], ah[mt], bh[nt][0], bh[nt][2]);
                mma16816(acc[mt][nt*2+1], ah[mt], bh[nt][1], bh[nt][3]);
            }
        uint32_t al[2][4];
#pragma unroll
        for (int mt = 0; mt < 2; ++mt)
            ldsm4(al[mt], a_base[mt] + bufoff + (A_LO - A_HI) + koff);
#pragma unroll
        for (int mt = 0; mt < 2; ++mt)
#pragma unroll
            for (int nt = 0; nt < 2; ++nt) {
                mma16816(acc[mt][nt*2+0], al[mt], bh[nt][0], bh[nt][2]);
                mma16816(acc[mt][nt*2+1], al[mt], bh[nt][1], bh[nt][3]);
            }
        uint32_t bl[2][4];
#pragma unroll
        for (int nt = 0; nt < 2; ++nt)
            ldsm4(bl[nt], b_base[nt] + bufoff + (B_LO - B_HI) + koff);
#pragma unroll
        for (int mt = 0; mt < 2; ++mt)
#pragma unroll
            for (int nt = 0; nt < 2; ++nt) {
                mma16816(acc[mt][nt*2+0], ah[mt], bl[nt][0], bl[nt][2]);
                mma16816(acc[mt][nt*2+1], ah[mt], bl[nt][1], bl[nt][3]);
            }
    }
}

// ---------------------------------------------------------------------------
// fused score kernel: scores[row] = sum_u tanh(hiddens@W1 + b1 + q)[u] * V[u]
// CTA: 128 rows x (8 passes of N=128), 16 warps 4(M)x4(N), 1 sync/chunk
// ---------------------------------------------------------------------------
__global__ void __launch_bounds__(NTHR, 1)
score_kernel(const float* __restrict__ b1, const float* __restrict__ V)
{
    extern __shared__ char smem[];
    const uint32_t sb = (uint32_t)__cvta_generic_to_shared(smem);
    const int tid  = threadIdx.x;
    const int lane = tid & 31;
    const int wid  = tid >> 5;
    const int wm   = wid >> 2;      // 0..3  -> M offset 32*wm
    const int wn   = wid & 3;       // 0..3  -> N offset 32*wn
    const int row0 = blockIdx.x * 128;
    const int b    = blockIdx.x >> 4;

    float* bqs  = (float*)(smem + OFF_BQ);
    float* vss  = (float*)(smem + OFF_VS);
    float* srow = (float*)(smem + OFF_SROW);
    for (int i = tid; i < Uu; i += NTHR) {
        bqs[i] = b1[i] + g_query[b * Uu + i];
        vss[i] = V[i];
    }
    if (tid < 128) srow[tid] = 0.f;

    // per-lane ldmatrix bases
    const int lrow = lane & 15;
    const int lk16 = (lane & 16);          // 0 or 16 bytes (k-halves)
    const int msk  = (lrow & 7) * 16;      // row-dependent xor mask
    uint32_t a_base[2], b_base[2];
#pragma unroll
    for (int mt = 0; mt < 2; ++mt)
        a_base[mt] = sb + OFF_TILE + A_HI + (wm * 32 + mt * 16 + lrow) * 128;
#pragma unroll
    for (int nt = 0; nt < 2; ++nt)
        b_base[nt] = sb + OFF_TILE + B_HI + (wn * 32 + nt * 16 + lrow) * 128;

    float sprt[4];
#pragma unroll
    for (int p = 0; p < 4; ++p) sprt[p] = 0.f;

    // prologue: chunk 0 into buffer 0
    load_chunk(row0, 0, 0, sb, 0, tid);
    CP_COMMIT();

    int g = 0;
    for (int ut = 0; ut < NPASS; ++ut) {
        float acc[2][4][4];
#pragma unroll
        for (int mt = 0; mt < 2; ++mt)
#pragma unroll
            for (int n = 0; n < 4; ++n)
#pragma unroll
                for (int c = 0; c < 4; ++c) acc[mt][n][c] = 0.f;

        for (int kc = 0; kc < NCHUNK; ++kc, ++g) {
            const uint32_t bufoff = (uint32_t)(g & 1) * BUF_SZ;

            CP_WAIT0();
            __syncthreads();   // data for g visible; buffer g-1 fully drained

            if (g + 1 < NPASS * NCHUNK) {
                const int nut = (kc == NCHUNK - 1) ? ut + 1 : ut;
                const int nkc = (kc == NCHUNK - 1) ? 0 : kc + 1;
                load_chunk(row0, nut * 128, nkc * 64, sb, bufoff ^ BUF_SZ, tid);
                CP_COMMIT();
            }

            compute_chunk(acc, a_base, b_base, msk, lk16, bufoff);

            if (kc == NCHUNK - 1) {
                // fused epilogue: tanh(key)*V partial row sums
#pragma unroll
                for (int mt = 0; mt < 2; ++mt)
#pragma unroll
                    for (int n8 = 0; n8 < 4; ++n8) {
                        const int u = ut * 128 + wn * 32 + n8 * 8 + (lane & 3) * 2;
                        const float q0 = bqs[u],     v0 = vss[u];
                        const float q1 = bqs[u + 1], v1 = vss[u + 1];
                        sprt[mt*2+0] += ftanh(acc[mt][n8][0] + q0) * v0
                                      + ftanh(acc[mt][n8][1] + q1) * v1;
                        sprt[mt*2+1] += ftanh(acc[mt][n8][2] + q0) * v0
                                      + ftanh(acc[mt][n8][3] + q1) * v1;
                    }
            }
        }
    }

    // reduce partial sums: quad shuffle then smem atomics across wn warps
    __syncthreads();
#pragma unroll
    for (int p = 0; p < 4; ++p) {
        float v = sprt[p];
        v += __shfl_xor_sync(0xffffffffu, v, 1);
        v += __shfl_xor_sync(0xffffffffu, v, 2);
        if ((lane & 3) == 0) {
            const int r = wm * 32 + (p >> 1) * 16 + (p & 1) * 8 + (lane >> 2);
            atomicAdd(&srow[r], v);
        }
    }
    __syncthreads();
    if (tid < 128) g_score[row0 + tid] = srow[tid];
}

// ---------------------------------------------------------------------------
// softmax over S per batch; weights -> d_out + g_score (in place)
// ---------------------------------------------------------------------------
__global__ void softmax_kernel(float* __restrict__ out)
{
    __shared__ float red[256];
    const int b = blockIdx.x;
    const int tid = threadIdx.x;
    float* sc = g_score + b * Ss;

    float m = -1e30f;
    for (int i = tid; i < Ss; i += 256) m = fmaxf(m, sc[i]);
    red[tid] = m;
    __syncthreads();
    for (int s = 128; s > 0; s >>= 1) {
        if (tid < s) red[tid] = fmaxf(red[tid], red[tid + s]);
        __syncthreads();
    }
    m = red[0];
    __syncthreads();

    float sum = 0.f;
    for (int i = tid; i < Ss; i += 256) {
        float e = expf(sc[i] - m);
        sc[i] = e;
        sum += e;
    }
    red[tid] = sum;
    __syncthreads();
    for (int s = 128; s > 0; s >>= 1) {
        if (tid < s) red[tid] += red[tid + s];
        __syncthreads();
    }
    const float inv = 1.f / red[0];
    __syncthreads();

    float* wout = out + Bb * Hh;
    for (int i = tid; i < Ss; i += 256) {
        const float w = sc[i] * inv;
        sc[i] = w;
        wout[b * Ss + i] = w;
    }
}

__global__ void zero_ctx_kernel(float* __restrict__ out)
{
    const int i = blockIdx.x * 256 + threadIdx.x;
    if (i < Bb * Hh) out[i] = 0.f;
}

__global__ void context_kernel(const float* __restrict__ hiddens,
                               float* __restrict__ out)
{
    const int b  = blockIdx.x;
    const int h  = blockIdx.y * 256 + threadIdx.x;
    const int s0 = blockIdx.z * (Ss / 8);

    const float* wp = g_score + b * Ss + s0;
    const float* hp = hiddens + ((size_t)(b * Ss + s0)) * Hh + h;

    float acc = 0.f;
#pragma unroll 4
    for (int s = 0; s < Ss / 8; ++s)
        acc += wp[s] * hp[(size_t)s * Hh];

    atomicAdd(&out[b * Hh + h], acc);
}

// ---------------------------------------------------------------------------
extern "C" void kernel_launch(void* const* d_in, const int* in_sizes, int n_in,
                              void* d_out, int out_size)
{
    const float* hidden_t = (const float*)d_in[0];
    const float* hiddens  = (const float*)d_in[1];
    const float* W1       = (const float*)d_in[2];
    const float* b1       = (const float*)d_in[3];
    const float* W2       = (const float*)d_in[4];
    const float* b2       = (const float*)d_in[5];
    const float* V        = (const float*)d_in[6];
    // d_in[7] = bV : constant shift, cancels in softmax -> unused

    float* out = (float*)d_out;

    cudaFuncSetAttribute(score_kernel,
                         cudaFuncAttributeMaxDynamicSharedMemorySize,
                         SMEM_TOTAL);

    a_split_kernel<<<(size_t)Mm * Hh / 4 / 256, 256>>>(hiddens);
    w1t_kernel<<<dim3(Hh / 32, Uu / 32), dim3(32, 8)>>>(W1);
    query_kernel<<<dim3(Bb, Uu / 128), 128>>>(hidden_t, W2, b2);
    score_kernel<<<(Bb * Ss) / 128, NTHR, SMEM_TOTAL>>>(b1, V);
    softmax_kernel<<<Bb, 256>>>(out);
    zero_ctx_kernel<<<(Bb * Hh + 255) / 256, 256>>>(out);
    context_kernel<<<dim3(Bb, Hh / 256, 8), 256>>>(hiddens, out);
}

// round 6
// speedup vs baseline: 1.3884x; 1.3884x over previous
#include <cuda_runtime.h>
#include <cuda_fp16.h>
#include <math.h>
#include <stdint.h>

#define Bb 32
#define Ss 2048
#define Hh 1024
#define Uu 1024
#define Mm (Bb*Ss)

// ---------------- device scratch (static, no runtime alloc) ----------------
__device__ float g_query[Bb*Uu];                     // q[b,u] = hidden_t@W2 + b2
__device__ float g_score[Bb*Ss];                     // scores -> softmax weights
__device__ __align__(16) __half g_w1t_hi[Uu*Hh];     // W1^T hi  [u][k]
__device__ __align__(16) __half g_a_hi[(size_t)Mm*Hh];  // hiddens hi [row][k]
__device__ __align__(16) __half g_a_lo[(size_t)Mm*Hh];  // hiddens lo [row][k]

// ---------------- PTX helpers (non-'a' features only: valid on sm_103) -----
__device__ __forceinline__ void cp_async16(uint32_t dst, const void* src) {
    asm volatile("cp.async.cg.shared.global [%0], [%1], 16;\n"
                 :: "r"(dst), "l"(src) : "memory");
}
#define CP_COMMIT() asm volatile("cp.async.commit_group;\n" ::: "memory")
#define CP_WAIT0()  asm volatile("cp.async.wait_group 0;\n" ::: "memory")

__device__ __forceinline__ void ldsm4(uint32_t r[4], uint32_t addr) {
    asm volatile("ldmatrix.sync.aligned.m8n8.x4.shared.b16 {%0,%1,%2,%3}, [%4];"
                 : "=r"(r[0]), "=r"(r[1]), "=r"(r[2]), "=r"(r[3]) : "r"(addr));
}
__device__ __forceinline__ void mma16816(float c[4], const uint32_t a[4],
                                         uint32_t b0, uint32_t b1) {
    asm volatile("mma.sync.aligned.m16n8k16.row.col.f32.f16.f16.f32 "
                 "{%0,%1,%2,%3}, {%4,%5,%6,%7}, {%8,%9}, {%0,%1,%2,%3};"
                 : "+f"(c[0]), "+f"(c[1]), "+f"(c[2]), "+f"(c[3])
                 : "r"(a[0]), "r"(a[1]), "r"(a[2]), "r"(a[3]), "r"(b0), "r"(b1));
}

__device__ __forceinline__ float ftanh(float x) {
    const float cx = fminf(fmaxf(x, -9.f), 9.f);
    const float e  = __expf(2.f * cx);
    return __fdividef(e - 1.f, e + 1.f);
}

// ---------------- SMEM layout ----------------
#define OFF_BQ   0
#define OFF_VS   4096
#define OFF_SROW 8192
#define OFF_TILE 8704
#define A_HI 0
#define A_LO 16384
#define B_HI 32768
#define BUF_SZ 65536      // A hi 16K | A lo 16K | B hi 32K (256 rows x 128B)
#define SMEM_TOTAL (OFF_TILE + 2*BUF_SZ)   // 139776 bytes

#define NPASS  4     // u-tiles of 256
#define NCHUNK 16    // K chunks of 64
#define NTHR   512   // 16 warps: 4(M) x 4(N), warp tile 32 x 64

// ---------------------------------------------------------------------------
// prep: hiddens fp32 -> fp16 hi/lo (coalesced, one float4 per thread)
// ---------------------------------------------------------------------------
__global__ void a_split_kernel(const float* __restrict__ hiddens)
{
    const size_t i = (size_t)blockIdx.x * 256 + threadIdx.x;  // float4 index
    const float4 v = ((const float4*)hiddens)[i];

    const __half hx = __float2half_rn(v.x), hy = __float2half_rn(v.y);
    const __half hz = __float2half_rn(v.z), hw = __float2half_rn(v.w);
    const __half lx = __float2half_rn(v.x - __half2float(hx));
    const __half ly = __float2half_rn(v.y - __half2float(hy));
    const __half lz = __float2half_rn(v.z - __half2float(hz));
    const __half lw = __float2half_rn(v.w - __half2float(hw));

    __half2 h01 = __halves2half2(hx, hy), h23 = __halves2half2(hz, hw);
    __half2 l01 = __halves2half2(lx, ly), l23 = __halves2half2(lz, lw);
    uint2 hv, lv;
    hv.x = *reinterpret_cast<uint32_t*>(&h01);
    hv.y = *reinterpret_cast<uint32_t*>(&h23);
    lv.x = *reinterpret_cast<uint32_t*>(&l01);
    lv.y = *reinterpret_cast<uint32_t*>(&l23);
    ((uint2*)g_a_hi)[i] = hv;
    ((uint2*)g_a_lo)[i] = lv;
}

// ---------------------------------------------------------------------------
// prep: W1^T hi (fp16) from W1 [H,U]
// ---------------------------------------------------------------------------
__global__ void w1t_kernel(const float* __restrict__ W1)
{
    __shared__ float t[32][33];
    const int k0 = blockIdx.x * 32, u0 = blockIdx.y * 32;
    const int x = threadIdx.x, y = threadIdx.y;   // 32 x 8
#pragma unroll
    for (int i = 0; i < 32; i += 8)
        t[y + i][x] = W1[(size_t)(k0 + y + i) * Uu + u0 + x];
    __syncthreads();
#pragma unroll
    for (int i = 0; i < 32; i += 8)
        g_w1t_hi[(size_t)(u0 + y + i) * Hh + k0 + x] = __float2half_rn(t[x][y + i]);
}

// ---------------------------------------------------------------------------
// query[b,u] = hidden_t@W2 + b2
// ---------------------------------------------------------------------------
__global__ void query_kernel(const float* __restrict__ hidden_t,
                             const float* __restrict__ W2,
                             const float* __restrict__ b2)
{
    __shared__ float ht[Hh];
    int b = blockIdx.x;
    int u = blockIdx.y * 128 + threadIdx.x;
    for (int i = threadIdx.x; i < Hh; i += 128) ht[i] = hidden_t[b * Hh + i];
    __syncthreads();
    float acc = b2[u];
#pragma unroll 8
    for (int h = 0; h < Hh; ++h)
        acc += ht[h] * W2[h * Uu + u];
    g_query[b * Uu + u] = acc;
}

// ---------------------------------------------------------------------------
// chunk loader: A hi/lo (128x64) + B hi (256x64) all via cp.async
// rows of 64 fp16 = 128B, xor-swizzled per 8-row group
// ---------------------------------------------------------------------------
__device__ __forceinline__ void load_chunk(int row0, int u0, int k0,
                                           uint32_t sb, uint32_t bufoff, int tid)
{
    const uint32_t base = sb + OFF_TILE + bufoff;
    // A: 128 rows x 8 segs: 1024 segs / 512 thr = 2 each (hi + lo)
#pragma unroll
    for (int i = 0; i < 2; ++i) {
        const int lin = i * NTHR + tid;
        const int n = lin >> 3, sg = lin & 7;
        const uint32_t off = (uint32_t)(n * 128 + ((sg * 16) ^ ((n & 7) * 16)));
        const size_t src = (size_t)(row0 + n) * Hh + k0 + sg * 8;
        cp_async16(base + A_HI + off, g_a_hi + src);
        cp_async16(base + A_LO + off, g_a_lo + src);
    }
    // B: 256 rows x 8 segs: 2048 segs / 512 thr = 4 each
#pragma unroll
    for (int i = 0; i < 4; ++i) {
        const int lin = i * NTHR + tid;
        const int n = lin >> 3, sg = lin & 7;
        const uint32_t off = (uint32_t)(n * 128 + ((sg * 16) ^ ((n & 7) * 16)));
        const size_t src = (size_t)(u0 + n) * Hh + k0 + sg * 8;
        cp_async16(base + B_HI + off, g_w1t_hi + src);
    }
}

// ---------------------------------------------------------------------------
// compute one K=64 chunk: acc += Ah*Bh + Al*Bh
// per warp: 32 rows (2 mt) x 64 cols (4 nt ldsm -> 8 n8)
// ---------------------------------------------------------------------------
__device__ __forceinline__ void compute_chunk(float acc[2][8][4],
                                              const uint32_t a_base[2],
                                              const uint32_t b_base[4],
                                              int msk, int lk16, uint32_t bufoff)
{
#pragma unroll
    for (int ks = 0; ks < 4; ++ks) {
        const uint32_t koff = (uint32_t)((ks * 32 + lk16) ^ msk);
        uint32_t ah[2][4], al[2][4], bh[4][4];
#pragma unroll
        for (int mt = 0; mt < 2; ++mt) {
            ldsm4(ah[mt], a_base[mt] + bufoff + koff);
            ldsm4(al[mt], a_base[mt] + bufoff + (A_LO - A_HI) + koff);
        }
#pragma unroll
        for (int nt = 0; nt < 4; ++nt) ldsm4(bh[nt], b_base[nt] + bufoff + koff);
#pragma unroll
        for (int mt = 0; mt < 2; ++mt)
#pragma unroll
            for (int nt = 0; nt < 4; ++nt) {
                mma16816(acc[mt][nt*2+0], ah[mt], bh[nt][0], bh[nt][2]);
                mma16816(acc[mt][nt*2+1], ah[mt], bh[nt][1], bh[nt][3]);
            }
#pragma unroll
        for (int mt = 0; mt < 2; ++mt)
#pragma unroll
            for (int nt = 0; nt < 4; ++nt) {
                mma16816(acc[mt][nt*2+0], al[mt], bh[nt][0], bh[nt][2]);
                mma16816(acc[mt][nt*2+1], al[mt], bh[nt][1], bh[nt][3]);
            }
    }
}

// ---------------------------------------------------------------------------
// fused score kernel: scores[row] = sum_u tanh(hiddens@W1 + b1 + q)[u] * V[u]
// CTA: 128 rows x (4 passes of N=256), 16 warps 4(M)x4(N), 1 sync/chunk
// ---------------------------------------------------------------------------
__global__ void __launch_bounds__(NTHR, 1)
score_kernel(const float* __restrict__ b1, const float* __restrict__ V)
{
    extern __shared__ char smem[];
    const uint32_t sb = (uint32_t)__cvta_generic_to_shared(smem);
    const int tid  = threadIdx.x;
    const int lane = tid & 31;
    const int wid  = tid >> 5;
    const int wm   = wid >> 2;      // 0..3  -> M offset 32*wm
    const int wn   = wid & 3;       // 0..3  -> N offset 64*wn
    const int row0 = blockIdx.x * 128;
    const int b    = blockIdx.x >> 4;

    float* bqs  = (float*)(smem + OFF_BQ);
    float* vss  = (float*)(smem + OFF_VS);
    float* srow = (float*)(smem + OFF_SROW);
    for (int i = tid; i < Uu; i += NTHR) {
        bqs[i] = b1[i] + g_query[b * Uu + i];
        vss[i] = V[i];
    }
    if (tid < 128) srow[tid] = 0.f;

    // per-lane ldmatrix bases
    const int lrow = lane & 15;
    const int lk16 = (lane & 16);          // 0 or 16 bytes (k-halves)
    const int msk  = (lrow & 7) * 16;      // row-dependent xor mask
    uint32_t a_base[2], b_base[4];
#pragma unroll
    for (int mt = 0; mt < 2; ++mt)
        a_base[mt] = sb + OFF_TILE + A_HI + (wm * 32 + mt * 16 + lrow) * 128;
#pragma unroll
    for (int nt = 0; nt < 4; ++nt)
        b_base[nt] = sb + OFF_TILE + B_HI + (wn * 64 + nt * 16 + lrow) * 128;

    float sprt[4];
#pragma unroll
    for (int p = 0; p < 4; ++p) sprt[p] = 0.f;

    // prologue: chunk 0 into buffer 0
    load_chunk(row0, 0, 0, sb, 0, tid);
    CP_COMMIT();

    int g = 0;
    for (int ut = 0; ut < NPASS; ++ut) {
        float acc[2][8][4];
#pragma unroll
        for (int mt = 0; mt < 2; ++mt)
#pragma unroll
            for (int n = 0; n < 8; ++n)
#pragma unroll
                for (int c = 0; c < 4; ++c) acc[mt][n][c] = 0.f;

        for (int kc = 0; kc < NCHUNK; ++kc, ++g) {
            const uint32_t bufoff = (uint32_t)(g & 1) * BUF_SZ;

            CP_WAIT0();
            __syncthreads();   // data for g visible; buffer g-1 fully drained

            if (g + 1 < NPASS * NCHUNK) {
                const int nut = (kc == NCHUNK - 1) ? ut + 1 : ut;
                const int nkc = (kc == NCHUNK - 1) ? 0 : kc + 1;
                load_chunk(row0, nut * 256, nkc * 64, sb, bufoff ^ BUF_SZ, tid);
                CP_COMMIT();
            }

            compute_chunk(acc, a_base, b_base, msk, lk16, bufoff);

            if (kc == NCHUNK - 1) {
                // fused epilogue: tanh(key)*V partial row sums
#pragma unroll
                for (int mt = 0; mt < 2; ++mt)
#pragma unroll
                    for (int n8 = 0; n8 < 8; ++n8) {
                        const int u = ut * 256 + wn * 64 + (n8 >> 1) * 16
                                    + (n8 & 1) * 8 + (lane & 3) * 2;
                        const float q0 = bqs[u],     v0 = vss[u];
                        const float q1 = bqs[u + 1], v1 = vss[u + 1];
                        sprt[mt*2+0] += ftanh(acc[mt][n8][0] + q0) * v0
                                      + ftanh(acc[mt][n8][1] + q1) * v1;
                        sprt[mt*2+1] += ftanh(acc[mt][n8][2] + q0) * v0
                                      + ftanh(acc[mt][n8][3] + q1) * v1;
                    }
            }
        }
    }

    // reduce partial sums: quad shuffle then smem atomics across wn warps
    __syncthreads();
#pragma unroll
    for (int p = 0; p < 4; ++p) {
        float v = sprt[p];
        v += __shfl_xor_sync(0xffffffffu, v, 1);
        v += __shfl_xor_sync(0xffffffffu, v, 2);
        if ((lane & 3) == 0) {
            const int r = wm * 32 + (p >> 1) * 16 + (p & 1) * 8 + (lane >> 2);
            atomicAdd(&srow[r], v);
        }
    }
    __syncthreads();
    if (tid < 128) g_score[row0 + tid] = srow[tid];
}

// ---------------------------------------------------------------------------
// softmax over S per batch; weights -> d_out + g_score (in place)
// ---------------------------------------------------------------------------
__global__ void softmax_kernel(float* __restrict__ out)
{
    __shared__ float red[256];
    const int b = blockIdx.x;
    const int tid = threadIdx.x;
    float* sc = g_score + b * Ss;

    float m = -1e30f;
    for (int i = tid; i < Ss; i += 256) m = fmaxf(m, sc[i]);
    red[tid] = m;
    __syncthreads();
    for (int s = 128; s > 0; s >>= 1) {
        if (tid < s) red[tid] = fmaxf(red[tid], red[tid + s]);
        __syncthreads();
    }
    m = red[0];
    __syncthreads();

    float sum = 0.f;
    for (int i = tid; i < Ss; i += 256) {
        float e = expf(sc[i] - m);
        sc[i] = e;
        sum += e;
    }
    red[tid] = sum;
    __syncthreads();
    for (int s = 128; s > 0; s >>= 1) {
        if (tid < s) red[tid] += red[tid + s];
        __syncthreads();
    }
    const float inv = 1.f / red[0];
    __syncthreads();

    float* wout = out + Bb * Hh;
    for (int i = tid; i < Ss; i += 256) {
        const float w = sc[i] * inv;
        sc[i] = w;
        wout[b * Ss + i] = w;
    }
}

__global__ void zero_ctx_kernel(float* __restrict__ out)
{
    const int i = blockIdx.x * 256 + threadIdx.x;
    if (i < Bb * Hh) out[i] = 0.f;
}

__global__ void context_kernel(const float* __restrict__ hiddens,
                               float* __restrict__ out)
{
    const int b  = blockIdx.x;
    const int h  = blockIdx.y * 256 + threadIdx.x;
    const int s0 = blockIdx.z * (Ss / 8);

    const float* wp = g_score + b * Ss + s0;
    const float* hp = hiddens + ((size_t)(b * Ss + s0)) * Hh + h;

    float acc = 0.f;
#pragma unroll 4
    for (int s = 0; s < Ss / 8; ++s)
        acc += wp[s] * hp[(size_t)s * Hh];

    atomicAdd(&out[b * Hh + h], acc);
}

// ---------------------------------------------------------------------------
extern "C" void kernel_launch(void* const* d_in, const int* in_sizes, int n_in,
                              void* d_out, int out_size)
{
    const float* hidden_t = (const float*)d_in[0];
    const float* hiddens  = (const float*)d_in[1];
    const float* W1       = (const float*)d_in[2];
    const float* b1       = (const float*)d_in[3];
    const float* W2       = (const float*)d_in[4];
    const float* b2       = (const float*)d_in[5];
    const float* V        = (const float*)d_in[6];
    // d_in[7] = bV : constant shift, cancels in softmax -> unused

    float* out = (float*)d_out;

    cudaFuncSetAttribute(score_kernel,
                         cudaFuncAttributeMaxDynamicSharedMemorySize,
                         SMEM_TOTAL);

    a_split_kernel<<<(size_t)Mm * Hh / 4 / 256, 256>>>(hiddens);
    w1t_kernel<<<dim3(Hh / 32, Uu / 32), dim3(32, 8)>>>(W1);
    query_kernel<<<dim3(Bb, Uu / 128), 128>>>(hidden_t, W2, b2);
    score_kernel<<<(Bb * Ss) / 128, NTHR, SMEM_TOTAL>>>(b1, V);
    softmax_kernel<<<Bb, 256>>>(out);
    zero_ctx_kernel<<<(Bb * Hh + 255) / 256, 256>>>(out);
    context_kernel<<<dim3(Bb, Hh / 256, 8), 256>>>(hiddens, out);
}